// round 1
// baseline (speedup 1.0000x reference)
#include <cuda_runtime.h>
#include <math.h>

#define BATCH 64
#define NPTS  512
#define DIM   512
#define CHUNKS 16                    // dist blocks per batch
#define DBLOCKS (BATCH * CHUNKS)     // 1024
#define DTHREADS 256
#define DWARPS (DTHREADS / 32)       // 8
#define APW (NPTS / CHUNKS / DWARPS) // 4 anchors per warp

__device__ __constant__ float c_margin = 0.3f;
__device__ __constant__ float c_eps    = 1e-6f;

// scratch (no allocations allowed)
__device__ int   g_pn[BATCH * NPTS];
__device__ float g_partial[DBLOCKS];
__device__ int   g_cnt[DBLOCKS];

// ---------------------------------------------------------------------------
// Kernel 1: per-(b,i) first positive / first negative index + anchor_ok flag.
// grid = BATCH blocks, NPTS threads.
// pos_mask[i][j] = (ids[j]==ids[i]) && j!=i && ids[j]>=0
// neg_mask[i][j] = (ids[j]!=ids[i]) && ids[j]>=0
// argmax(bool) == first true index, else 0.
// ---------------------------------------------------------------------------
__global__ void mask_kernel(const int* __restrict__ ids)
{
    __shared__ int s_ids[NPTS];
    const int b = blockIdx.x;
    const int i = threadIdx.x;

    const int myid = ids[b * NPTS + i];
    s_ids[i] = myid;
    // barrier + count of valid ids in this batch (for the `enough >= 2` test)
    const int nvalid = __syncthreads_count(myid >= 0);

    int pos = -1, neg = -1;
    for (int j = 0; j < NPTS; ++j) {
        const int idj = s_ids[j];
        if (idj >= 0) {
            if (pos < 0 && idj == myid && j != i) pos = j;
            if (neg < 0 && idj != myid)           neg = j;
            if (pos >= 0 && neg >= 0) break;
        }
    }
    const int ok = (myid >= 0) && (pos >= 0) && (neg >= 0) && (nvalid >= 2);
    const int p = (pos < 0) ? 0 : pos;
    const int n = (neg < 0) ? 0 : neg;
    g_pn[b * NPTS + i] = p | (n << 10) | (ok << 20);
}

// ---------------------------------------------------------------------------
// Kernel 2: distances + masked hinge accumulation.
// grid = BATCH*CHUNKS blocks, 256 threads (8 warps), 1 warp -> 4 anchors.
// ---------------------------------------------------------------------------
__global__ void dist_kernel(const float* __restrict__ feats)
{
    const int bk    = blockIdx.x;
    const int b     = bk / CHUNKS;
    const int chunk = bk % CHUNKS;
    const int wid   = threadIdx.x >> 5;
    const int lane  = threadIdx.x & 31;

    __shared__ float s_tot;
    __shared__ int   s_cnt;
    if (threadIdx.x == 0) { s_tot = 0.0f; s_cnt = 0; }
    __syncthreads();

    float w_tot = 0.0f;
    int   w_cnt = 0;

    const int a_base = chunk * (NPTS / CHUNKS) + wid * APW;
    const float eps = c_eps;

    for (int a = 0; a < APW; ++a) {
        const int i  = a_base + a;
        const int pn = g_pn[b * NPTS + i];
        if (!(pn >> 20)) continue;
        const int p = pn & 1023;
        const int n = (pn >> 10) & 1023;

        const float4* __restrict__ fi =
            (const float4*)(feats + ((size_t)b * NPTS + i) * DIM);
        const float4* __restrict__ fp =
            (const float4*)(feats + ((size_t)b * NPTS + p) * DIM);
        const float4* __restrict__ fn =
            (const float4*)(feats + ((size_t)b * NPTS + n) * DIM);

        float sap = 0.0f, san = 0.0f;
        #pragma unroll
        for (int k = 0; k < DIM / 4 / 32; ++k) {
            const int idx = k * 32 + lane;
            const float4 a4 = fi[idx];
            const float4 p4 = fp[idx];
            const float4 n4 = fn[idx];
            float d;
            d = a4.x - p4.x + eps; sap = fmaf(d, d, sap);
            d = a4.y - p4.y + eps; sap = fmaf(d, d, sap);
            d = a4.z - p4.z + eps; sap = fmaf(d, d, sap);
            d = a4.w - p4.w + eps; sap = fmaf(d, d, sap);
            d = a4.x - n4.x + eps; san = fmaf(d, d, san);
            d = a4.y - n4.y + eps; san = fmaf(d, d, san);
            d = a4.z - n4.z + eps; san = fmaf(d, d, san);
            d = a4.w - n4.w + eps; san = fmaf(d, d, san);
        }
        // warp reduce both sums
        #pragma unroll
        for (int o = 16; o > 0; o >>= 1) {
            sap += __shfl_xor_sync(0xFFFFFFFFu, sap, o);
            san += __shfl_xor_sync(0xFFFFFFFFu, san, o);
        }
        if (lane == 0) {
            const float per = sqrtf(sap) - sqrtf(san) + c_margin;
            if (per > 0.0f) w_tot += per;
            w_cnt++;
        }
    }

    if (lane == 0) {
        atomicAdd(&s_tot, w_tot);
        atomicAdd(&s_cnt, w_cnt);
    }
    __syncthreads();
    if (threadIdx.x == 0) {
        g_partial[bk] = s_tot;
        g_cnt[bk]     = s_cnt;
    }
}

// ---------------------------------------------------------------------------
// Kernel 3: final reduction of 1024 partials -> 3 output scalars.
// ---------------------------------------------------------------------------
__global__ void finish_kernel(float* __restrict__ out, int out_size)
{
    __shared__ float st[DBLOCKS];
    __shared__ int   sc[DBLOCKS];
    const int t = threadIdx.x;
    st[t] = g_partial[t];
    sc[t] = g_cnt[t];
    __syncthreads();
    #pragma unroll
    for (int s = DBLOCKS / 2; s > 0; s >>= 1) {
        if (t < s) { st[t] += st[t + s]; sc[t] += sc[t + s]; }
        __syncthreads();
    }
    if (t == 0) {
        const int cnt = sc[0];
        const float loss = (cnt > 0) ? (st[0] / (float)cnt) : 0.0f;
        // (tracking_loss, loss_triplet, loss_id); LAMBDA_TRIPLET = 1, loss_id = 0
        if (out_size > 0) out[0] = loss;
        if (out_size > 1) out[1] = loss;
        if (out_size > 2) out[2] = 0.0f;
    }
}

extern "C" void kernel_launch(void* const* d_in, const int* in_sizes, int n_in,
                              void* d_out, int out_size)
{
    const float* feats = (const float*)d_in[0];
    const int*   ids   = (const int*)d_in[1];
    float*       out   = (float*)d_out;

    mask_kernel<<<BATCH, NPTS>>>(ids);
    dist_kernel<<<DBLOCKS, DTHREADS>>>(feats);
    finish_kernel<<<1, DBLOCKS>>>(out, out_size);
}

// round 2
// speedup vs baseline: 2.4741x; 2.4741x over previous
#include <cuda_runtime.h>
#include <math.h>

#define BATCH 64
#define NPTS  512
#define DIM   512
#define NIDS  32                     // track ids are in [-1, 32)
#define CHUNKS 16                    // dist blocks per batch
#define DBLOCKS (BATCH * CHUNKS)     // 1024
#define DTHREADS 256
#define DWARPS (DTHREADS / 32)       // 8
#define APW (NPTS / CHUNKS / DWARPS) // 4 anchors per warp

__device__ __constant__ float c_margin = 0.3f;
__device__ __constant__ float c_eps    = 1e-6f;

// scratch (no allocations allowed)
__device__ float g_partial[DBLOCKS];
__device__ int   g_cnt[DBLOCKS];

// ---------------------------------------------------------------------------
// Fused kernel: per-batch id tables (redundant per block, cheap) + distances.
// grid = BATCH*CHUNKS blocks, 256 threads (8 warps), 1 warp -> 4 anchors.
//
// Closed-form replacement for argmax-of-mask (ids in [-1, 32)):
//   pos(i) = first[m] != i ? first[m] : second[m]     (needs count[m] >= 2)
//   neg(i) = ids[j1] != m ? j1 : j2                   (needs nvalid > count[m])
//   ok(i)  = m >= 0 && count[m] >= 2 && nvalid - count[m] >= 1 && nvalid >= 2
// ---------------------------------------------------------------------------
__global__ void dist_kernel(const float* __restrict__ feats,
                            const int*   __restrict__ ids)
{
    const int bk    = blockIdx.x;
    const int b     = bk / CHUNKS;
    const int chunk = bk % CHUNKS;
    const int wid   = threadIdx.x >> 5;
    const int lane  = threadIdx.x & 31;
    const int t     = threadIdx.x;

    __shared__ int s_first[NIDS];
    __shared__ int s_second[NIDS];
    __shared__ int s_count[NIDS];
    __shared__ int s_j1;      // first valid index overall
    __shared__ int s_j2;      // first valid index with id != ids[j1]
    __shared__ int s_idj1;    // ids[j1]
    __shared__ int s_nvalid;
    __shared__ float s_tot;
    __shared__ int   s_cnt;

    if (t < NIDS) {
        s_first[t]  = 0x7fffffff;
        s_second[t] = 0x7fffffff;
        s_count[t]  = 0;
    }
    if (t == 0) {
        s_j1 = 0x7fffffff;
        s_j2 = 0x7fffffff;
        s_nvalid = 0;
        s_tot = 0.0f;
        s_cnt = 0;
    }
    __syncthreads();

    // Pass 1: first occurrence per id, per-id counts, first valid overall.
    const int   i0 = t;
    const int   i1 = t + DTHREADS;
    const int   id0 = ids[b * NPTS + i0];
    const int   id1 = ids[b * NPTS + i1];
    if (id0 >= 0) {
        atomicMin(&s_first[id0], i0);
        atomicAdd(&s_count[id0], 1);
        atomicMin(&s_j1, i0);
    }
    if (id1 >= 0) {
        atomicMin(&s_first[id1], i1);
        atomicAdd(&s_count[id1], 1);
        atomicMin(&s_j1, i1);
    }
    int nv = __syncthreads_count(id0 >= 0);
    nv    += __syncthreads_count(id1 >= 0);
    if (t == 0) {
        s_nvalid = nv;
        s_idj1 = (s_j1 < NPTS) ? ids[b * NPTS + s_j1] : -2;
    }
    __syncthreads();

    // Pass 2: second occurrence per id; first valid with id != ids[j1].
    const int idj1 = s_idj1;
    if (id0 >= 0) {
        if (i0 != s_first[id0]) atomicMin(&s_second[id0], i0);
        if (id0 != idj1)        atomicMin(&s_j2, i0);
    }
    if (id1 >= 0) {
        if (i1 != s_first[id1]) atomicMin(&s_second[id1], i1);
        if (id1 != idj1)        atomicMin(&s_j2, i1);
    }
    __syncthreads();

    const int nvalid = s_nvalid;
    const int j1 = s_j1;
    const int j2 = s_j2;

    float w_tot = 0.0f;
    int   w_cnt = 0;

    const int a_base = chunk * (NPTS / CHUNKS) + wid * APW;
    const float eps = c_eps;

    for (int a = 0; a < APW; ++a) {
        const int i = a_base + a;
        const int m = ids[b * NPTS + i];          // hot in L1/L2
        if (m < 0) continue;
        const int cm = s_count[m];
        if (cm < 2) continue;                      // no positive
        if (nvalid - cm < 1) continue;             // no negative
        // (nvalid >= 2 implied by cm >= 2)

        const int f = s_first[m];
        const int p = (f != i) ? f : s_second[m];
        const int n = (idj1 != m) ? j1 : j2;

        const float4* __restrict__ fi =
            (const float4*)(feats + ((size_t)b * NPTS + i) * DIM);
        const float4* __restrict__ fp =
            (const float4*)(feats + ((size_t)b * NPTS + p) * DIM);
        const float4* __restrict__ fn =
            (const float4*)(feats + ((size_t)b * NPTS + n) * DIM);

        float sap = 0.0f, san = 0.0f;
        #pragma unroll
        for (int k = 0; k < DIM / 4 / 32; ++k) {
            const int idx = k * 32 + lane;
            const float4 a4 = fi[idx];
            const float4 p4 = fp[idx];
            const float4 n4 = fn[idx];
            float d;
            d = a4.x - p4.x + eps; sap = fmaf(d, d, sap);
            d = a4.y - p4.y + eps; sap = fmaf(d, d, sap);
            d = a4.z - p4.z + eps; sap = fmaf(d, d, sap);
            d = a4.w - p4.w + eps; sap = fmaf(d, d, sap);
            d = a4.x - n4.x + eps; san = fmaf(d, d, san);
            d = a4.y - n4.y + eps; san = fmaf(d, d, san);
            d = a4.z - n4.z + eps; san = fmaf(d, d, san);
            d = a4.w - n4.w + eps; san = fmaf(d, d, san);
        }
        #pragma unroll
        for (int o = 16; o > 0; o >>= 1) {
            sap += __shfl_xor_sync(0xFFFFFFFFu, sap, o);
            san += __shfl_xor_sync(0xFFFFFFFFu, san, o);
        }
        if (lane == 0) {
            const float per = sqrtf(sap) - sqrtf(san) + c_margin;
            if (per > 0.0f) w_tot += per;
            w_cnt++;
        }
    }

    if (lane == 0) {
        atomicAdd(&s_tot, w_tot);
        atomicAdd(&s_cnt, w_cnt);
    }
    __syncthreads();
    if (t == 0) {
        g_partial[bk] = s_tot;
        g_cnt[bk]     = s_cnt;
    }
}

// ---------------------------------------------------------------------------
// Final reduction of 1024 partials -> 3 output scalars.
// ---------------------------------------------------------------------------
__global__ void finish_kernel(float* __restrict__ out, int out_size)
{
    __shared__ float st[DBLOCKS];
    __shared__ int   sc[DBLOCKS];
    const int t = threadIdx.x;
    st[t] = g_partial[t];
    sc[t] = g_cnt[t];
    __syncthreads();
    #pragma unroll
    for (int s = DBLOCKS / 2; s > 0; s >>= 1) {
        if (t < s) { st[t] += st[t + s]; sc[t] += sc[t + s]; }
        __syncthreads();
    }
    if (t == 0) {
        const int cnt = sc[0];
        const float loss = (cnt > 0) ? (st[0] / (float)cnt) : 0.0f;
        // (tracking_loss, loss_triplet, loss_id); LAMBDA_TRIPLET = 1, loss_id = 0
        if (out_size > 0) out[0] = loss;
        if (out_size > 1) out[1] = loss;
        if (out_size > 2) out[2] = 0.0f;
    }
}

extern "C" void kernel_launch(void* const* d_in, const int* in_sizes, int n_in,
                              void* d_out, int out_size)
{
    const float* feats = (const float*)d_in[0];
    const int*   ids   = (const int*)d_in[1];
    float*       out   = (float*)d_out;

    dist_kernel<<<DBLOCKS, DTHREADS>>>(feats, ids);
    finish_kernel<<<1, DBLOCKS>>>(out, out_size);
}